// round 5
// baseline (speedup 1.0000x reference)
#include <cuda_runtime.h>

#define T_LEN 4995
#define BATCH 64
#define VOCAB 4096
#define EDIM  100
#define UDIM  64
#define G3    192   // 3*U gate width
#define NTHR  768

// Precomputed (emb @ W1 + b1[0]) table: [VOCAB, 192]
__device__ __align__(16) float g_tab[VOCAB * G3];

__device__ __forceinline__ void ffma2(float2& acc, const float2 a, const float2 b) {
    asm("fma.rn.f32x2 %0, %1, %2, %0;"
        : "+l"(reinterpret_cast<unsigned long long&>(acc))
        : "l"(*reinterpret_cast<const unsigned long long*>(&a)),
          "l"(*reinterpret_cast<const unsigned long long*>(&b)));
}

__device__ __forceinline__ float sigf(float x) {
    return 1.0f / (1.0f + __expf(-x));
}
__device__ __forceinline__ float tanh_fast(float x) {
    float e = __expf(2.0f * x);
    return (e - 1.0f) * __fdividef(1.0f, e + 1.0f);
}

// ---------------------------------------------------------------------------
// Kernel 1: g_tab[v][j] = sum_e emb[v][e] * W1[e][j] + b1[0][j]
// ---------------------------------------------------------------------------
__global__ void build_tab(const float* __restrict__ emb,
                          const float* __restrict__ W1,
                          const float* __restrict__ b1) {
    __shared__ float es[EDIM];
    const int v = blockIdx.x;
    const int j = threadIdx.x;
    for (int e = j; e < EDIM; e += G3) es[e] = emb[v * EDIM + e];
    __syncthreads();
    float s = b1[j];
#pragma unroll 4
    for (int e = 0; e < EDIM; e++) s += es[e] * __ldg(&W1[e * G3 + j]);
    g_tab[v * G3 + j] = s;
}

// ---------------------------------------------------------------------------
// Kernel 2: fused 2-layer GRU, skewed pipeline, one CTA per batch row.
// 768 threads = 24 warps, 6 per SMSP (2 of each role) for latency hiding.
//
// Slot s (single __syncthreads per slot, all roles concurrent):
//   role A (tid   0..255): h1[s]   = GRU1(h1[s-1], xt[s])
//   role C (tid 256..511): x2[s-1] = h1[s-1] @ W2 + b2[0]  + cp.async xt[s+3]
//   role B (tid 512..767): h2[s-2] = GRU2gate(h2[s-3], x2[s-2])
// Each column handled by a lane QUAD (quarter-dots of 16, 2-level shfl.xor).
// ---------------------------------------------------------------------------
__global__ void __launch_bounds__(NTHR, 1)
gru_fused(const int*   __restrict__ tokens,
          const float* __restrict__ U1w,
          const float* __restrict__ b1,
          const float* __restrict__ W2w,
          const float* __restrict__ U2w,
          const float* __restrict__ b2,
          const float* __restrict__ Wout,
          const float* __restrict__ bout,
          float*       __restrict__ out) {
    __shared__ int   toks[T_LEN];
    __shared__ __align__(16) float h1s[2][UDIM];   // double-buffered h1
    __shared__ __align__(16) float h2s[2][UDIM];   // double-buffered h2
    __shared__ __align__(16) float x2s[2][G3];     // double-buffered x2
    __shared__ __align__(16) float xtr[4][G3];     // xt ring, prefetch distance 3
    __shared__ __align__(16) float red[UDIM];

    const int tid = threadIdx.x;
    const int b   = blockIdx.x;

    if (tid < UDIM) {
        h1s[0][tid] = 0.0f; h1s[1][tid] = 0.0f;
        h2s[0][tid] = 0.0f; h2s[1][tid] = 0.0f;
    }
    for (int i = tid; i < T_LEN; i += NTHR)
        toks[i] = tokens[(long long)b * T_LEN + i];
    __syncthreads();
    if (tid < 3 * G3) {
        const int tp = tid / G3, jj = tid % G3;
        xtr[tp][jj] = g_tab[toks[tp] * G3 + jj];
    }
    __syncthreads();

    const int role = tid >> 8;        // 0: A(layer1), 1: C(x2), 2: B(layer2)
    const int t2   = tid & 255;
    const int col  = t2 >> 2;         // 0..63
    const int q    = t2 & 3;          // quarter index

    // ---- per-thread register weights: quarter-dot (16 k-values) x 3 gates --
    const float* Wm = (role == 0) ? U1w : (role == 1) ? W2w : U2w;
    float2 w[3][8];
#pragma unroll
    for (int g = 0; g < 3; g++)
#pragma unroll
        for (int m = 0; m < 8; m++) {
            const int k = q * 16 + 2 * m;
            w[g][m] = make_float2(Wm[k * G3 + g * 64 + col],
                                  Wm[(k + 1) * G3 + g * 64 + col]);
        }
    float bias[3];
#pragma unroll
    for (int g = 0; g < 3; g++) {
        float bv;
        if (role == 0)      bv = b1[G3 + g * 64 + col];   // recurrent bias L1
        else if (role == 1) bv = b2[g * 64 + col];        // input bias L2
        else                bv = b2[G3 + g * 64 + col];   // recurrent bias L2
        bias[g] = (q == 0) ? bv : 0.0f;
    }

    for (int s = 0; s < T_LEN + 2; s++) {
        // Which h-buffer this role reads this slot (state from previous slot)
        if (role == 0) {
            if (s < T_LEN) {
                // h1[s] from h1[s-1] (buffer (s+1)&1) and xt[s]
                const float4* hv4 = (const float4*)(h1s[(s + 1) & 1]) + q * 4;
                const float4 v0 = hv4[0], v1 = hv4[1], v2 = hv4[2], v3 = hv4[3];
                const float2 hh0 = {v0.x, v0.y}, hh1 = {v0.z, v0.w};
                const float2 hh2 = {v1.x, v1.y}, hh3 = {v1.z, v1.w};
                const float2 hh4 = {v2.x, v2.y}, hh5 = {v2.z, v2.w};
                const float2 hh6 = {v3.x, v3.y}, hh7 = {v3.z, v3.w};
                float2 a0 = {bias[0], 0.f}, a1 = {0.f, 0.f};
                float2 r0 = {bias[1], 0.f}, r1 = {0.f, 0.f};
                float2 c0 = {bias[2], 0.f}, c1 = {0.f, 0.f};
                ffma2(a0, hh0, w[0][0]); ffma2(a1, hh1, w[0][1]);
                ffma2(r0, hh0, w[1][0]); ffma2(r1, hh1, w[1][1]);
                ffma2(c0, hh0, w[2][0]); ffma2(c1, hh1, w[2][1]);
                ffma2(a0, hh2, w[0][2]); ffma2(a1, hh3, w[0][3]);
                ffma2(r0, hh2, w[1][2]); ffma2(r1, hh3, w[1][3]);
                ffma2(c0, hh2, w[2][2]); ffma2(c1, hh3, w[2][3]);
                ffma2(a0, hh4, w[0][4]); ffma2(a1, hh5, w[0][5]);
                ffma2(r0, hh4, w[1][4]); ffma2(r1, hh5, w[1][5]);
                ffma2(c0, hh4, w[2][4]); ffma2(c1, hh5, w[2][5]);
                ffma2(a0, hh6, w[0][6]); ffma2(a1, hh7, w[0][7]);
                ffma2(r0, hh6, w[1][6]); ffma2(r1, hh7, w[1][7]);
                ffma2(c0, hh6, w[2][6]); ffma2(c1, hh7, w[2][7]);
                float az = a0.x + a0.y + a1.x + a1.y;
                float ar = r0.x + r0.y + r1.x + r1.y;
                float ah = c0.x + c0.y + c1.x + c1.y;
                az += __shfl_xor_sync(0xFFFFFFFFu, az, 1);
                ar += __shfl_xor_sync(0xFFFFFFFFu, ar, 1);
                ah += __shfl_xor_sync(0xFFFFFFFFu, ah, 1);
                az += __shfl_xor_sync(0xFFFFFFFFu, az, 2);
                ar += __shfl_xor_sync(0xFFFFFFFFu, ar, 2);
                ah += __shfl_xor_sync(0xFFFFFFFFu, ah, 2);
                const float xz = xtr[s & 3][col];
                const float xr = xtr[s & 3][64 + col];
                const float xh = xtr[s & 3][128 + col];
                const float z  = sigf(xz + az);
                const float r  = sigf(xr + ar);
                const float hh = tanh_fast(xh + r * ah);
                const float hold = h1s[(s + 1) & 1][col];
                if (q == 0)
                    h1s[s & 1][col] = z * hold + (1.0f - z) * hh;
            }
        } else if (role == 1) {
            // -------- async prefetch of xt for slot s+3 (16B x 48 lanes) ----
            if (t2 < 48) {
                const int tp = s + 3;
                if (tp < T_LEN) {
                    const int tok = toks[tp];
                    const float* src = g_tab + tok * G3 + t2 * 4;
                    unsigned dst = (unsigned)__cvta_generic_to_shared(
                        &xtr[tp & 3][t2 * 4]);
                    asm volatile("cp.async.cg.shared.global [%0], [%1], 16;"
                                 :: "r"(dst), "l"(src) : "memory");
                }
                asm volatile("cp.async.commit_group;" ::: "memory");
            }
            if (s >= 1 && s <= T_LEN) {
                // x2[s-1] = h1[s-1] @ W2 + b2[0]; h1[s-1] in buffer (s-1)&1
                const float4* hv4 = (const float4*)(h1s[(s + 1) & 1]) + q * 4;
                const float4 v0 = hv4[0], v1 = hv4[1], v2 = hv4[2], v3 = hv4[3];
                const float2 hh0 = {v0.x, v0.y}, hh1 = {v0.z, v0.w};
                const float2 hh2 = {v1.x, v1.y}, hh3 = {v1.z, v1.w};
                const float2 hh4 = {v2.x, v2.y}, hh5 = {v2.z, v2.w};
                const float2 hh6 = {v3.x, v3.y}, hh7 = {v3.z, v3.w};
                float2 a0 = {bias[0], 0.f}, a1 = {0.f, 0.f};
                float2 r0 = {bias[1], 0.f}, r1 = {0.f, 0.f};
                float2 c0 = {bias[2], 0.f}, c1 = {0.f, 0.f};
                ffma2(a0, hh0, w[0][0]); ffma2(a1, hh1, w[0][1]);
                ffma2(r0, hh0, w[1][0]); ffma2(r1, hh1, w[1][1]);
                ffma2(c0, hh0, w[2][0]); ffma2(c1, hh1, w[2][1]);
                ffma2(a0, hh2, w[0][2]); ffma2(a1, hh3, w[0][3]);
                ffma2(r0, hh2, w[1][2]); ffma2(r1, hh3, w[1][3]);
                ffma2(c0, hh2, w[2][2]); ffma2(c1, hh3, w[2][3]);
                ffma2(a0, hh4, w[0][4]); ffma2(a1, hh5, w[0][5]);
                ffma2(r0, hh4, w[1][4]); ffma2(r1, hh5, w[1][5]);
                ffma2(c0, hh4, w[2][4]); ffma2(c1, hh5, w[2][5]);
                ffma2(a0, hh6, w[0][6]); ffma2(a1, hh7, w[0][7]);
                ffma2(r0, hh6, w[1][6]); ffma2(r1, hh7, w[1][7]);
                ffma2(c0, hh6, w[2][6]); ffma2(c1, hh7, w[2][7]);
                float sz = a0.x + a0.y + a1.x + a1.y;
                float sr = r0.x + r0.y + r1.x + r1.y;
                float sh = c0.x + c0.y + c1.x + c1.y;
                sz += __shfl_xor_sync(0xFFFFFFFFu, sz, 1);
                sr += __shfl_xor_sync(0xFFFFFFFFu, sr, 1);
                sh += __shfl_xor_sync(0xFFFFFFFFu, sh, 1);
                sz += __shfl_xor_sync(0xFFFFFFFFu, sz, 2);
                sr += __shfl_xor_sync(0xFFFFFFFFu, sr, 2);
                sh += __shfl_xor_sync(0xFFFFFFFFu, sh, 2);
                if (q == 0) {
                    float* dst = x2s[(s + 1) & 1];   // buffer (s-1)&1
                    dst[col]       = sz;
                    dst[64 + col]  = sr;
                    dst[128 + col] = sh;
                }
            }
            if (t2 < 48)
                asm volatile("cp.async.wait_group 2;" ::: "memory");
        } else {
            if (s >= 2 && s <= T_LEN + 1) {
                // h2[s-2] from h2[s-3] (buffer (s-1)&1) and x2[s-2] (buffer s&1)
                const float4* hv4 = (const float4*)(h2s[(s + 1) & 1]) + q * 4;
                const float4 v0 = hv4[0], v1 = hv4[1], v2 = hv4[2], v3 = hv4[3];
                const float2 hh0 = {v0.x, v0.y}, hh1 = {v0.z, v0.w};
                const float2 hh2 = {v1.x, v1.y}, hh3 = {v1.z, v1.w};
                const float2 hh4 = {v2.x, v2.y}, hh5 = {v2.z, v2.w};
                const float2 hh6 = {v3.x, v3.y}, hh7 = {v3.z, v3.w};
                float2 a0 = {bias[0], 0.f}, a1 = {0.f, 0.f};
                float2 r0 = {bias[1], 0.f}, r1 = {0.f, 0.f};
                float2 c0 = {bias[2], 0.f}, c1 = {0.f, 0.f};
                ffma2(a0, hh0, w[0][0]); ffma2(a1, hh1, w[0][1]);
                ffma2(r0, hh0, w[1][0]); ffma2(r1, hh1, w[1][1]);
                ffma2(c0, hh0, w[2][0]); ffma2(c1, hh1, w[2][1]);
                ffma2(a0, hh2, w[0][2]); ffma2(a1, hh3, w[0][3]);
                ffma2(r0, hh2, w[1][2]); ffma2(r1, hh3, w[1][3]);
                ffma2(c0, hh2, w[2][2]); ffma2(c1, hh3, w[2][3]);
                ffma2(a0, hh4, w[0][4]); ffma2(a1, hh5, w[0][5]);
                ffma2(r0, hh4, w[1][4]); ffma2(r1, hh5, w[1][5]);
                ffma2(c0, hh4, w[2][4]); ffma2(c1, hh5, w[2][5]);
                ffma2(a0, hh6, w[0][6]); ffma2(a1, hh7, w[0][7]);
                ffma2(r0, hh6, w[1][6]); ffma2(r1, hh7, w[1][7]);
                ffma2(c0, hh6, w[2][6]); ffma2(c1, hh7, w[2][7]);
                float az = a0.x + a0.y + a1.x + a1.y;
                float ar = r0.x + r0.y + r1.x + r1.y;
                float ah = c0.x + c0.y + c1.x + c1.y;
                az += __shfl_xor_sync(0xFFFFFFFFu, az, 1);
                ar += __shfl_xor_sync(0xFFFFFFFFu, ar, 1);
                ah += __shfl_xor_sync(0xFFFFFFFFu, ah, 1);
                az += __shfl_xor_sync(0xFFFFFFFFu, az, 2);
                ar += __shfl_xor_sync(0xFFFFFFFFu, ar, 2);
                ah += __shfl_xor_sync(0xFFFFFFFFu, ah, 2);
                const float xz = x2s[s & 1][col];
                const float xr = x2s[s & 1][64 + col];
                const float xh = x2s[s & 1][128 + col];
                const float z  = sigf(xz + az);
                const float r  = sigf(xr + ar);
                const float hh = tanh_fast(xh + r * ah);
                const float hold = h2s[(s + 1) & 1][col];
                if (q == 0)
                    h2s[s & 1][col] = z * hold + (1.0f - z) * hh;
            }
        }
        __syncthreads();
    }

    // ---------------- Epilogue: sigmoid(h2[T-1] @ Wout + bout) ----------------
    if (tid < UDIM) red[tid] = h2s[(T_LEN + 1) & 1][tid] * Wout[tid];
    __syncthreads();
    if (tid == 0) {
        float s = bout[0];
#pragma unroll
        for (int k = 0; k < UDIM; k++) s += red[k];
        out[b] = 1.0f / (1.0f + __expf(-s));
    }
}

// ---------------------------------------------------------------------------
extern "C" void kernel_launch(void* const* d_in, const int* in_sizes, int n_in,
                              void* d_out, int out_size) {
    const int*   tokens = (const int*)  d_in[0];
    const float* emb    = (const float*)d_in[1];
    const float* W1     = (const float*)d_in[2];
    const float* U1     = (const float*)d_in[3];
    const float* b1     = (const float*)d_in[4];
    const float* W2     = (const float*)d_in[5];
    const float* U2     = (const float*)d_in[6];
    const float* b2     = (const float*)d_in[7];
    const float* Wout   = (const float*)d_in[8];
    const float* bout   = (const float*)d_in[9];

    build_tab<<<VOCAB, G3>>>(emb, W1, b1);
    gru_fused<<<BATCH, NTHR>>>(tokens, U1, b1, W2, U2, b2, Wout, bout,
                               (float*)d_out);
}

// round 6
// speedup vs baseline: 1.8811x; 1.8811x over previous
#include <cuda_runtime.h>

#define T_LEN 4995
#define BATCH 64
#define VOCAB 4096
#define EDIM  100
#define UDIM  64
#define G3    192   // 3*U gate width
#define NTHR  384
#define KSLOT 2500  // slots of 2 timesteps

// Precomputed (emb @ W1 + b1[0]) table: [VOCAB, 192]
__device__ __align__(16) float g_tab[VOCAB * G3];

__device__ __forceinline__ void ffma2(float2& acc, const float2 a, const float2 b) {
    asm("fma.rn.f32x2 %0, %1, %2, %0;"
        : "+l"(reinterpret_cast<unsigned long long&>(acc))
        : "l"(*reinterpret_cast<const unsigned long long*>(&a)),
          "l"(*reinterpret_cast<const unsigned long long*>(&b)));
}

__device__ __forceinline__ float sigf(float x) {
    return __fdividef(1.0f, 1.0f + __expf(-x));
}
__device__ __forceinline__ float tanh_fast(float x) {
    float e = __expf(2.0f * x);
    return (e - 1.0f) * __fdividef(1.0f, e + 1.0f);
}

// Pair-split 3-gate dot: each lane does a half-dot (32 k) for 3 gates,
// then combines with its partner lane via shfl.xor 1.
__device__ __forceinline__ void dot3(const float2* __restrict__ hv,
                                     const float2 w[3][16],
                                     float bz, float br, float bh,
                                     float& s0, float& s1, float& s2) {
    float2 a0 = {bz, 0.f}, a1 = {0.f, 0.f};
    float2 r0 = {br, 0.f}, r1 = {0.f, 0.f};
    float2 c0 = {bh, 0.f}, c1 = {0.f, 0.f};
#pragma unroll
    for (int m = 0; m < 16; m += 2) {
        const float2 h0 = hv[m], h1v = hv[m + 1];
        ffma2(a0, h0, w[0][m]); ffma2(a1, h1v, w[0][m + 1]);
        ffma2(r0, h0, w[1][m]); ffma2(r1, h1v, w[1][m + 1]);
        ffma2(c0, h0, w[2][m]); ffma2(c1, h1v, w[2][m + 1]);
    }
    s0 = a0.x + a0.y + a1.x + a1.y;
    s1 = r0.x + r0.y + r1.x + r1.y;
    s2 = c0.x + c0.y + c1.x + c1.y;
    s0 += __shfl_xor_sync(0xFFFFFFFFu, s0, 1);
    s1 += __shfl_xor_sync(0xFFFFFFFFu, s1, 1);
    s2 += __shfl_xor_sync(0xFFFFFFFFu, s2, 1);
}

// ---------------------------------------------------------------------------
// Kernel 1: g_tab[v][j] = sum_e emb[v][e] * W1[e][j] + b1[0][j]
// ---------------------------------------------------------------------------
__global__ void build_tab(const float* __restrict__ emb,
                          const float* __restrict__ W1,
                          const float* __restrict__ b1) {
    __shared__ float es[EDIM];
    const int v = blockIdx.x;
    const int j = threadIdx.x;
    for (int e = j; e < EDIM; e += G3) es[e] = emb[v * EDIM + e];
    __syncthreads();
    float s = b1[j];
#pragma unroll 4
    for (int e = 0; e < EDIM; e++) s += es[e] * __ldg(&W1[e * G3 + j]);
    g_tab[v * G3 + j] = s;
}

// ---------------------------------------------------------------------------
// Kernel 2: fused 2-layer GRU, skewed pipeline, 2 timesteps per CTA barrier.
//
// Slot k (one __syncthreads; role-local named barriers inside A and B):
//   role A (tid   0..127): h1[2k], (bar 1) h1[2k+1]
//   role C (tid 128..255): cp.async xt[2k+6..2k+7]; x2[2k-2], x2[2k-1] (indep)
//   role B (tid 256..383): h2[2k-4], (bar 2) h2[2k-3]
// Rings: h1/h2/x2 mod 4, xt mod 8 (prefetch distance 3 slots).
// ---------------------------------------------------------------------------
__global__ void __launch_bounds__(NTHR, 1)
gru_fused(const int*   __restrict__ tokens,
          const float* __restrict__ U1w,
          const float* __restrict__ b1,
          const float* __restrict__ W2w,
          const float* __restrict__ U2w,
          const float* __restrict__ b2,
          const float* __restrict__ Wout,
          const float* __restrict__ bout,
          float*       __restrict__ out) {
    __shared__ int   toks[T_LEN];
    __shared__ __align__(16) float h1s[4][UDIM];
    __shared__ __align__(16) float h2s[4][UDIM];
    __shared__ __align__(16) float x2s[4][G3];
    __shared__ __align__(16) float xtr[8][G3];
    __shared__ __align__(16) float red[UDIM];

    const int tid = threadIdx.x;
    const int b   = blockIdx.x;

    if (tid < UDIM) {
        h1s[3][tid] = 0.0f;   // h1[-1]
        h2s[3][tid] = 0.0f;   // h2[-1]
    }
    for (int i = tid; i < T_LEN; i += NTHR)
        toks[i] = tokens[(long long)b * T_LEN + i];
    __syncthreads();
    // Preload xt for steps 0..5 (first 3 slots)
    for (int i = tid; i < 6 * G3; i += NTHR) {
        const int tp = i / G3, jj = i % G3;
        xtr[tp][jj] = g_tab[toks[tp] * G3 + jj];
    }
    __syncthreads();

    const int role = tid >> 7;        // 0: A(layer1), 1: C(x2+prefetch), 2: B(layer2)
    const int t2   = tid & 127;
    const int col  = t2 >> 1;         // 0..63
    const int half = t2 & 1;

    // ---- per-thread register weights: half-dot (32 k-values) x 3 gates ----
    const float* Wm = (role == 0) ? U1w : (role == 1) ? W2w : U2w;
    float2 w[3][16];
#pragma unroll
    for (int g = 0; g < 3; g++)
#pragma unroll
        for (int m = 0; m < 16; m++) {
            const int k = half * 32 + 2 * m;
            w[g][m] = make_float2(Wm[k * G3 + g * 64 + col],
                                  Wm[(k + 1) * G3 + g * 64 + col]);
        }
    float bias[3];
#pragma unroll
    for (int g = 0; g < 3; g++) {
        float bv;
        if (role == 0)      bv = b1[G3 + g * 64 + col];   // recurrent bias L1
        else if (role == 1) bv = b2[g * 64 + col];        // input bias L2
        else                bv = b2[G3 + g * 64 + col];   // recurrent bias L2
        bias[g] = (half == 0) ? bv : 0.0f;
    }

    for (int k = 0; k < KSLOT; k++) {
        if (role == 0) {
            // ---------------- layer-1: steps 2k, 2k+1 ----------------
#pragma unroll
            for (int sub = 0; sub < 2; sub++) {
                const int s = 2 * k + sub;
                if (s < T_LEN) {
                    const float2* hv = (const float2*)(h1s[(s - 1) & 3]) + half * 16;
                    float az, ar, ah;
                    dot3(hv, w, bias[0], bias[1], bias[2], az, ar, ah);
                    const float xz = xtr[s & 7][col];
                    const float xr = xtr[s & 7][64 + col];
                    const float xh = xtr[s & 7][128 + col];
                    const float z  = sigf(xz + az);
                    const float r  = sigf(xr + ar);
                    const float hh = tanh_fast(xh + r * ah);
                    const float hold = h1s[(s - 1) & 3][col];
                    if (half == 0)
                        h1s[s & 3][col] = z * hold + (1.0f - z) * hh;
                }
                if (sub == 0)
                    asm volatile("bar.sync 1, 128;" ::: "memory");
            }
        } else if (role == 1) {
            // -------- async prefetch xt for steps 2k+6, 2k+7 (96 lanes) -----
            if (t2 < 96) {
                const int l48 = (t2 < 48) ? t2 : (t2 - 48);
                const int tp  = 2 * k + 6 + (t2 >= 48 ? 1 : 0);
                if (tp < T_LEN) {
                    const int tok = toks[tp];
                    const float* src = g_tab + tok * G3 + l48 * 4;
                    unsigned dst = (unsigned)__cvta_generic_to_shared(
                        &xtr[tp & 7][l48 * 4]);
                    asm volatile("cp.async.cg.shared.global [%0], [%1], 16;"
                                 :: "r"(dst), "l"(src) : "memory");
                }
                asm volatile("cp.async.commit_group;" ::: "memory");
            }
            // -------- x2[2k-2], x2[2k-1]: independent, full ILP -------------
#pragma unroll
            for (int sub = 0; sub < 2; sub++) {
                const int s = 2 * k - 2 + sub;
                if (s >= 0 && s < T_LEN) {
                    const float2* hv = (const float2*)(h1s[s & 3]) + half * 16;
                    float sz, sr, sh;
                    dot3(hv, w, bias[0], bias[1], bias[2], sz, sr, sh);
                    if (half == 0) {
                        float* dst = x2s[s & 3];
                        dst[col]       = sz;
                        dst[64 + col]  = sr;
                        dst[128 + col] = sh;
                    }
                }
            }
            if (t2 < 96)
                asm volatile("cp.async.wait_group 2;" ::: "memory");
        } else {
            // ---------------- layer-2: steps 2k-4, 2k-3 ----------------
#pragma unroll
            for (int sub = 0; sub < 2; sub++) {
                const int s = 2 * k - 4 + sub;
                if (s >= 0 && s < T_LEN) {
                    const float2* hv = (const float2*)(h2s[(s - 1) & 3]) + half * 16;
                    float az, ar, ah;
                    dot3(hv, w, bias[0], bias[1], bias[2], az, ar, ah);
                    const float xz = x2s[s & 3][col];
                    const float xr = x2s[s & 3][64 + col];
                    const float xh = x2s[s & 3][128 + col];
                    const float z  = sigf(xz + az);
                    const float r  = sigf(xr + ar);
                    const float hh = tanh_fast(xh + r * ah);
                    const float hold = h2s[(s - 1) & 3][col];
                    if (half == 0)
                        h2s[s & 3][col] = z * hold + (1.0f - z) * hh;
                }
                if (sub == 0)
                    asm volatile("bar.sync 2, 128;" ::: "memory");
            }
        }
        __syncthreads();
    }

    // ---------------- Epilogue: sigmoid(h2[T-1] @ Wout + bout) ----------------
    if (tid < UDIM) red[tid] = h2s[(T_LEN - 1) & 3][tid] * Wout[tid];
    __syncthreads();
    if (tid == 0) {
        float s = bout[0];
#pragma unroll
        for (int k = 0; k < UDIM; k++) s += red[k];
        out[b] = 1.0f / (1.0f + __expf(-s));
    }
}

// ---------------------------------------------------------------------------
extern "C" void kernel_launch(void* const* d_in, const int* in_sizes, int n_in,
                              void* d_out, int out_size) {
    const int*   tokens = (const int*)  d_in[0];
    const float* emb    = (const float*)d_in[1];
    const float* W1     = (const float*)d_in[2];
    const float* U1     = (const float*)d_in[3];
    const float* b1     = (const float*)d_in[4];
    const float* W2     = (const float*)d_in[5];
    const float* U2     = (const float*)d_in[6];
    const float* b2     = (const float*)d_in[7];
    const float* Wout   = (const float*)d_in[8];
    const float* bout   = (const float*)d_in[9];

    build_tab<<<VOCAB, G3>>>(emb, W1, b1);
    gru_fused<<<BATCH, NTHR>>>(tokens, U1, b1, W2, U2, b2, Wout, bout,
                               (float*)d_out);
}

// round 8
// speedup vs baseline: 1.9887x; 1.0572x over previous
#include <cuda_runtime.h>

#define T_LEN 4995
#define BATCH 64
#define VOCAB 4096
#define EDIM  100
#define UDIM  64
#define G3    192    // 3*U gate width
#define NTHR  384
#define KSLOT 1251   // slots of 4 timesteps

// Precomputed (emb @ W1 + b1[0]) table: [VOCAB, 192]
__device__ __align__(16) float g_tab[VOCAB * G3];

__device__ __forceinline__ void ffma2(float2& acc, const float2 a, const float2 b) {
    asm("fma.rn.f32x2 %0, %1, %2, %0;"
        : "+l"(reinterpret_cast<unsigned long long&>(acc))
        : "l"(*reinterpret_cast<const unsigned long long*>(&a)),
          "l"(*reinterpret_cast<const unsigned long long*>(&b)));
}

__device__ __forceinline__ float ex2a(float x) {
    float y; asm("ex2.approx.f32 %0, %1;" : "=f"(y) : "f"(x)); return y;
}
__device__ __forceinline__ float rcpa(float x) {
    float y; asm("rcp.approx.f32 %0, %1;" : "=f"(y) : "f"(x)); return y;
}
#define L2E 1.442695040889634f
__device__ __forceinline__ float sigf(float x) {
    return rcpa(1.0f + ex2a(-L2E * x));          // 1/(1+e^-x)
}
__device__ __forceinline__ float tanh_fast(float x) {
    return fmaf(-2.0f, rcpa(1.0f + ex2a(2.0f * L2E * x)), 1.0f);  // 1-2/(1+e^2x)
}

// Pair-split 3-gate dot: each lane does a half-dot (32 k) for 3 gates,
// then combines with its partner lane via shfl.xor 1.
__device__ __forceinline__ void dot3(const float2* __restrict__ hv,
                                     const float2 w[3][16],
                                     float bz, float br, float bh,
                                     float& s0, float& s1, float& s2) {
    float2 a0 = {bz, 0.f}, a1 = {0.f, 0.f};
    float2 r0 = {br, 0.f}, r1 = {0.f, 0.f};
    float2 c0 = {bh, 0.f}, c1 = {0.f, 0.f};
#pragma unroll
    for (int m = 0; m < 16; m += 2) {
        const float2 h0 = hv[m], h1v = hv[m + 1];
        ffma2(a0, h0, w[0][m]); ffma2(a1, h1v, w[0][m + 1]);
        ffma2(r0, h0, w[1][m]); ffma2(r1, h1v, w[1][m + 1]);
        ffma2(c0, h0, w[2][m]); ffma2(c1, h1v, w[2][m + 1]);
    }
    s0 = a0.x + a0.y + a1.x + a1.y;
    s1 = r0.x + r0.y + r1.x + r1.y;
    s2 = c0.x + c0.y + c1.x + c1.y;
    s0 += __shfl_xor_sync(0xFFFFFFFFu, s0, 1);
    s1 += __shfl_xor_sync(0xFFFFFFFFu, s1, 1);
    s2 += __shfl_xor_sync(0xFFFFFFFFu, s2, 1);
}

// ---------------------------------------------------------------------------
// Kernel 1: g_tab[v][j] = sum_e emb[v][e] * W1[e][j] + b1[0][j]
// ---------------------------------------------------------------------------
__global__ void build_tab(const float* __restrict__ emb,
                          const float* __restrict__ W1,
                          const float* __restrict__ b1) {
    __shared__ float es[EDIM];
    const int v = blockIdx.x;
    const int j = threadIdx.x;
    for (int e = j; e < EDIM; e += G3) es[e] = emb[v * EDIM + e];
    __syncthreads();
    float s = b1[j];
#pragma unroll 4
    for (int e = 0; e < EDIM; e++) s += es[e] * __ldg(&W1[e * G3 + j]);
    g_tab[v * G3 + j] = s;
}

// ---------------------------------------------------------------------------
// Kernel 2: fused 2-layer GRU, skewed pipeline, 4 timesteps per CTA barrier.
//
// Slot k (one __syncthreads; named bars inside A and B between sub-steps):
//   role A (tid   0..127): h1[4k .. 4k+3]           (3x bar.sync 1,128)
//   role C (tid 128..255): cp.async xt[4k+12..4k+15]; x2[4k-4 .. 4k-1] (indep)
//   role B (tid 256..383): h2[4k-8 .. 4k-5]          (3x bar.sync 2,128)
// Rings: h1/h2/x2 mod 8, xt mod 16 (prefetch distance 3 slots = 12 steps).
// ---------------------------------------------------------------------------
__global__ void __launch_bounds__(NTHR, 1)
gru_fused(const int*   __restrict__ tokens,
          const float* __restrict__ U1w,
          const float* __restrict__ b1,
          const float* __restrict__ W2w,
          const float* __restrict__ U2w,
          const float* __restrict__ b2,
          const float* __restrict__ Wout,
          const float* __restrict__ bout,
          float*       __restrict__ out) {
    __shared__ int   toks[T_LEN];
    __shared__ __align__(16) float h1s[8][UDIM];
    __shared__ __align__(16) float h2s[8][UDIM];
    __shared__ __align__(16) float x2s[8][G3];
    __shared__ __align__(16) float xtr[16][G3];
    __shared__ __align__(16) float red[UDIM];

    const int tid = threadIdx.x;
    const int b   = blockIdx.x;

    if (tid < UDIM) {
        h1s[7][tid] = 0.0f;   // h1[-1]
        h2s[7][tid] = 0.0f;   // h2[-1]
    }
    for (int i = tid; i < T_LEN; i += NTHR)
        toks[i] = tokens[(long long)b * T_LEN + i];
    __syncthreads();
    // Preload xt for steps 0..11 (first 3 slots)
    for (int i = tid; i < 12 * G3; i += NTHR) {
        const int tp = i / G3, jj = i % G3;
        xtr[tp][jj] = g_tab[toks[tp] * G3 + jj];
    }
    __syncthreads();

    const int role = tid >> 7;        // 0: A(layer1), 1: C(x2+prefetch), 2: B(layer2)
    const int t2   = tid & 127;
    const int col  = t2 >> 1;         // 0..63
    const int half = t2 & 1;

    // ---- per-thread register weights: half-dot (32 k-values) x 3 gates ----
    const float* Wm = (role == 0) ? U1w : (role == 1) ? W2w : U2w;
    float2 w[3][16];
#pragma unroll
    for (int g = 0; g < 3; g++)
#pragma unroll
        for (int m = 0; m < 16; m++) {
            const int k = half * 32 + 2 * m;
            w[g][m] = make_float2(Wm[k * G3 + g * 64 + col],
                                  Wm[(k + 1) * G3 + g * 64 + col]);
        }
    float bias[3];
#pragma unroll
    for (int g = 0; g < 3; g++) {
        float bv;
        if (role == 0)      bv = b1[G3 + g * 64 + col];   // recurrent bias L1
        else if (role == 1) bv = b2[g * 64 + col];        // input bias L2
        else                bv = b2[G3 + g * 64 + col];   // recurrent bias L2
        bias[g] = (half == 0) ? bv : 0.0f;
    }

    for (int k = 0; k < KSLOT; k++) {
        if (role == 0) {
            // ---------------- layer-1: steps 4k .. 4k+3 ----------------
#pragma unroll
            for (int sub = 0; sub < 4; sub++) {
                const int s = 4 * k + sub;
                if (s < T_LEN) {
                    const float2* hv = (const float2*)(h1s[(s - 1) & 7]) + half * 16;
                    float az, ar, ah;
                    dot3(hv, w, bias[0], bias[1], bias[2], az, ar, ah);
                    const float xz = xtr[s & 15][col];
                    const float xr = xtr[s & 15][64 + col];
                    const float xh = xtr[s & 15][128 + col];
                    const float z  = sigf(xz + az);
                    const float r  = sigf(xr + ar);
                    const float hh = tanh_fast(xh + r * ah);
                    const float hold = h1s[(s - 1) & 7][col];
                    if (half == 0)
                        h1s[s & 7][col] = z * hold + (1.0f - z) * hh;
                }
                if (sub < 3)
                    asm volatile("bar.sync 1, 128;" ::: "memory");
            }
        } else if (role == 1) {
            // ---- async prefetch xt for steps 4k+12..4k+15 (192 x 16B) ----
            {
                // chunk c in [0,192): step 4k+12 + c/48, 16B at (c%48)*16
                const int c0 = t2;
                const int tp0 = 4 * k + 12 + (c0 / 48);
                if (tp0 < T_LEN) {
                    const int tok = toks[tp0];
                    const float* src = g_tab + tok * G3 + (c0 % 48) * 4;
                    unsigned dst = (unsigned)__cvta_generic_to_shared(
                        &xtr[tp0 & 15][(c0 % 48) * 4]);
                    asm volatile("cp.async.cg.shared.global [%0], [%1], 16;"
                                 :: "r"(dst), "l"(src) : "memory");
                }
                if (t2 < 64) {
                    const int c1 = t2 + 128;
                    const int tp1 = 4 * k + 12 + (c1 / 48);
                    if (tp1 < T_LEN) {
                        const int tok = toks[tp1];
                        const float* src = g_tab + tok * G3 + (c1 % 48) * 4;
                        unsigned dst = (unsigned)__cvta_generic_to_shared(
                            &xtr[tp1 & 15][(c1 % 48) * 4]);
                        asm volatile("cp.async.cg.shared.global [%0], [%1], 16;"
                                     :: "r"(dst), "l"(src) : "memory");
                    }
                }
                asm volatile("cp.async.commit_group;" ::: "memory");
            }
            // -------- x2[4k-4 .. 4k-1]: independent, full ILP -------------
#pragma unroll
            for (int sub = 0; sub < 4; sub++) {
                const int s = 4 * k - 4 + sub;
                if (s >= 0 && s < T_LEN) {
                    const float2* hv = (const float2*)(h1s[s & 7]) + half * 16;
                    float sz, sr, sh;
                    dot3(hv, w, bias[0], bias[1], bias[2], sz, sr, sh);
                    if (half == 0) {
                        float* dst = x2s[s & 7];
                        dst[col]       = sz;
                        dst[64 + col]  = sr;
                        dst[128 + col] = sh;
                    }
                }
            }
            asm volatile("cp.async.wait_group 2;" ::: "memory");
        } else {
            // ---------------- layer-2: steps 4k-8 .. 4k-5 ----------------
#pragma unroll
            for (int sub = 0; sub < 4; sub++) {
                const int s = 4 * k - 8 + sub;
                if (s >= 0 && s < T_LEN) {
                    const float2* hv = (const float2*)(h2s[(s - 1) & 7]) + half * 16;
                    float az, ar, ah;
                    dot3(hv, w, bias[0], bias[1], bias[2], az, ar, ah);
                    const float xz = x2s[s & 7][col];
                    const float xr = x2s[s & 7][64 + col];
                    const float xh = x2s[s & 7][128 + col];
                    const float z  = sigf(xz + az);
                    const float r  = sigf(xr + ar);
                    const float hh = tanh_fast(xh + r * ah);
                    const float hold = h2s[(s - 1) & 7][col];
                    if (half == 0)
                        h2s[s & 7][col] = z * hold + (1.0f - z) * hh;
                }
                if (sub < 3)
                    asm volatile("bar.sync 2, 128;" ::: "memory");
            }
        }
        __syncthreads();
    }

    // ---------------- Epilogue: sigmoid(h2[T-1] @ Wout + bout) ----------------
    if (tid < UDIM) red[tid] = h2s[(T_LEN - 1) & 7][tid] * Wout[tid];
    __syncthreads();
    if (tid == 0) {
        float s = bout[0];
#pragma unroll
        for (int k = 0; k < UDIM; k++) s += red[k];
        out[b] = 1.0f / (1.0f + __expf(-s));
    }
}

// ---------------------------------------------------------------------------
extern "C" void kernel_launch(void* const* d_in, const int* in_sizes, int n_in,
                              void* d_out, int out_size) {
    const int*   tokens = (const int*)  d_in[0];
    const float* emb    = (const float*)d_in[1];
    const float* W1     = (const float*)d_in[2];
    const float* U1     = (const float*)d_in[3];
    const float* b1     = (const float*)d_in[4];
    const float* W2     = (const float*)d_in[5];
    const float* U2     = (const float*)d_in[6];
    const float* b2     = (const float*)d_in[7];
    const float* Wout   = (const float*)d_in[8];
    const float* bout   = (const float*)d_in[9];

    build_tab<<<VOCAB, G3>>>(emb, W1, b1);
    gru_fused<<<BATCH, NTHR>>>(tokens, U1, b1, W2, U2, b2, Wout, bout,
                               (float*)d_out);
}

// round 11
// speedup vs baseline: 2.3906x; 1.2021x over previous
#include <cuda_runtime.h>

#define T_LEN 4995
#define BATCH 64
#define VOCAB 4096
#define EDIM  100
#define UDIM  64
#define G3    192    // 3*U gate width
#define NTHR  384
#define KSLOT 1251   // slots of 4 timesteps

// Precomputed (emb @ W1 + b1[0]) table: [VOCAB, 192]
__device__ __align__(16) float g_tab[VOCAB * G3];

__device__ __forceinline__ void ffma2(float2& acc, const float2 a, const float2 b) {
    asm("fma.rn.f32x2 %0, %1, %2, %0;"
        : "+l"(reinterpret_cast<unsigned long long&>(acc))
        : "l"(*reinterpret_cast<const unsigned long long*>(&a)),
          "l"(*reinterpret_cast<const unsigned long long*>(&b)));
}
__device__ __forceinline__ float2 fadd2(const float2 a, const float2 b) {
    float2 r;
    asm("add.rn.f32x2 %0, %1, %2;"
        : "=l"(reinterpret_cast<unsigned long long&>(r))
        : "l"(*reinterpret_cast<const unsigned long long*>(&a)),
          "l"(*reinterpret_cast<const unsigned long long*>(&b)));
    return r;
}

__device__ __forceinline__ float tanha(float x) {
    float y; asm("tanh.approx.f32 %0, %1;" : "=f"(y) : "f"(x)); return y;
}
__device__ __forceinline__ float sigf(float x) {
    return fmaf(tanha(0.5f * x), 0.5f, 0.5f);    // 0.5*tanh(x/2)+0.5
}

// Pair-split 3-gate dot: each lane does a half-dot (32 k) for 3 gates,
// h loaded as 8x LDS.128, combine with partner lane via shfl.xor 1.
__device__ __forceinline__ void dot3(const float4* __restrict__ hv4,
                                     const float2 w[3][16],
                                     float bz, float br, float bh,
                                     float& s0, float& s1, float& s2) {
    float2 h[16];
#pragma unroll
    for (int m = 0; m < 8; m++) {
        const float4 v = hv4[m];
        h[2 * m]     = make_float2(v.x, v.y);
        h[2 * m + 1] = make_float2(v.z, v.w);
    }
    float2 a0 = {bz, 0.f}, a1 = {0.f, 0.f};
    float2 r0 = {br, 0.f}, r1 = {0.f, 0.f};
    float2 c0 = {bh, 0.f}, c1 = {0.f, 0.f};
#pragma unroll
    for (int m = 0; m < 16; m += 2) {
        ffma2(a0, h[m], w[0][m]); ffma2(a1, h[m + 1], w[0][m + 1]);
        ffma2(r0, h[m], w[1][m]); ffma2(r1, h[m + 1], w[1][m + 1]);
        ffma2(c0, h[m], w[2][m]); ffma2(c1, h[m + 1], w[2][m + 1]);
    }
    const float2 sa = fadd2(a0, a1), sr = fadd2(r0, r1), sc = fadd2(c0, c1);
    s0 = sa.x + sa.y;
    s1 = sr.x + sr.y;
    s2 = sc.x + sc.y;
    s0 += __shfl_xor_sync(0xFFFFFFFFu, s0, 1);
    s1 += __shfl_xor_sync(0xFFFFFFFFu, s1, 1);
    s2 += __shfl_xor_sync(0xFFFFFFFFu, s2, 1);
}

// ---------------------------------------------------------------------------
// Kernel 1: g_tab[v][j] = sum_e emb[v][e] * W1[e][j] + b1[0][j]
// ---------------------------------------------------------------------------
__global__ void build_tab(const float* __restrict__ emb,
                          const float* __restrict__ W1,
                          const float* __restrict__ b1) {
    __shared__ float es[EDIM];
    const int v = blockIdx.x;
    const int j = threadIdx.x;
    for (int e = j; e < EDIM; e += G3) es[e] = emb[v * EDIM + e];
    __syncthreads();
    float s = b1[j];
#pragma unroll 4
    for (int e = 0; e < EDIM; e++) s += es[e] * __ldg(&W1[e * G3 + j]);
    g_tab[v * G3 + j] = s;
}

// ---------------------------------------------------------------------------
// Kernel 2: fused 2-layer GRU, skewed pipeline, 4 timesteps per CTA barrier.
//
// Slot k (one __syncthreads; named bars inside A and B between sub-steps):
//   role A (tid   0..127): h1[4k .. 4k+3]           (3x bar.sync 1,128)
//   role C (tid 128..255): cp.async xt[4k+12..4k+15]; x2[4k-4 .. 4k-1] (indep)
//   role B (tid 256..383): h2[4k-8 .. 4k-5]          (3x bar.sync 2,128)
// Rings: h1/h2/x2 mod 8, xt mod 16 (prefetch distance 3 slots = 12 steps).
// ---------------------------------------------------------------------------
__global__ void __launch_bounds__(NTHR, 1)
gru_fused(const int*   __restrict__ tokens,
          const float* __restrict__ U1w,
          const float* __restrict__ b1,
          const float* __restrict__ W2w,
          const float* __restrict__ U2w,
          const float* __restrict__ b2,
          const float* __restrict__ Wout,
          const float* __restrict__ bout,
          float*       __restrict__ out) {
    __shared__ int   toks[T_LEN];
    __shared__ __align__(16) float h1s[8][UDIM];
    __shared__ __align__(16) float h2s[8][UDIM];
    __shared__ __align__(16) float x2s[8][G3];
    __shared__ __align__(16) float xtr[16][G3];
    __shared__ __align__(16) float red[UDIM];

    const int tid = threadIdx.x;
    const int b   = blockIdx.x;

    if (tid < UDIM) {
        h1s[7][tid] = 0.0f;   // h1[-1]
        h2s[7][tid] = 0.0f;   // h2[-1]
    }
    for (int i = tid; i < T_LEN; i += NTHR)
        toks[i] = tokens[(long long)b * T_LEN + i];
    __syncthreads();
    // Preload xt for steps 0..11 (first 3 slots)
    for (int i = tid; i < 12 * G3; i += NTHR) {
        const int tp = i / G3, jj = i % G3;
        xtr[tp][jj] = g_tab[toks[tp] * G3 + jj];
    }
    __syncthreads();

    const int role = tid >> 7;        // 0: A(layer1), 1: C(x2+prefetch), 2: B(layer2)
    const int t2   = tid & 127;
    const int col  = t2 >> 1;         // 0..63
    const int half = t2 & 1;

    // ---- per-thread register weights: half-dot (32 k-values) x 3 gates ----
    const float* Wm = (role == 0) ? U1w : (role == 1) ? W2w : U2w;
    float2 w[3][16];
#pragma unroll
    for (int g = 0; g < 3; g++)
#pragma unroll
        for (int m = 0; m < 16; m++) {
            const int k = half * 32 + 2 * m;
            w[g][m] = make_float2(Wm[k * G3 + g * 64 + col],
                                  Wm[(k + 1) * G3 + g * 64 + col]);
        }
    float bias[3];
#pragma unroll
    for (int g = 0; g < 3; g++) {
        float bv;
        if (role == 0)      bv = b1[G3 + g * 64 + col];   // recurrent bias L1
        else if (role == 1) bv = b2[g * 64 + col];        // input bias L2
        else                bv = b2[G3 + g * 64 + col];   // recurrent bias L2
        bias[g] = (half == 0) ? bv : 0.0f;
    }

    for (int k = 0; k < KSLOT; k++) {
        if (role == 0) {
            // ---------------- layer-1: steps 4k .. 4k+3 ----------------
#pragma unroll
            for (int sub = 0; sub < 4; sub++) {
                const int s = 4 * k + sub;
                if (s < T_LEN) {
                    const float4* hv4 = (const float4*)(h1s[(s - 1) & 7]) + half * 8;
                    const float xz = xtr[s & 15][col];
                    const float xr = xtr[s & 15][64 + col];
                    const float xh = xtr[s & 15][128 + col];
                    float az, ar, ah;
                    dot3(hv4, w, bias[0], bias[1], bias[2], az, ar, ah);
                    const float z  = sigf(xz + az);
                    const float r  = sigf(xr + ar);
                    const float hh = tanha(fmaf(r, ah, xh));
                    const float hold = h1s[(s - 1) & 7][col];
                    if (half == 0)
                        h1s[s & 7][col] = fmaf(z, hold - hh, hh);
                }
                if (sub < 3)
                    asm volatile("bar.sync 1, 128;" ::: "memory");
            }
        } else if (role == 1) {
            // ---- async prefetch xt for steps 4k+12..4k+15 (192 x 16B) ----
            {
                const int c0 = t2;
                const int tp0 = 4 * k + 12 + (c0 / 48);
                if (tp0 < T_LEN) {
                    const int tok = toks[tp0];
                    const float* src = g_tab + tok * G3 + (c0 % 48) * 4;
                    unsigned dst = (unsigned)__cvta_generic_to_shared(
                        &xtr[tp0 & 15][(c0 % 48) * 4]);
                    asm volatile("cp.async.cg.shared.global [%0], [%1], 16;"
                                 :: "r"(dst), "l"(src) : "memory");
                }
                if (t2 < 64) {
                    const int c1 = t2 + 128;
                    const int tp1 = 4 * k + 12 + (c1 / 48);
                    if (tp1 < T_LEN) {
                        const int tok = toks[tp1];
                        const float* src = g_tab + tok * G3 + (c1 % 48) * 4;
                        unsigned dst = (unsigned)__cvta_generic_to_shared(
                            &xtr[tp1 & 15][(c1 % 48) * 4]);
                        asm volatile("cp.async.cg.shared.global [%0], [%1], 16;"
                                     :: "r"(dst), "l"(src) : "memory");
                    }
                }
                asm volatile("cp.async.commit_group;" ::: "memory");
            }
            // -------- x2[4k-4 .. 4k-1]: independent, full ILP -------------
#pragma unroll
            for (int sub = 0; sub < 4; sub++) {
                const int s = 4 * k - 4 + sub;
                if (s >= 0 && s < T_LEN) {
                    const float4* hv4 = (const float4*)(h1s[s & 7]) + half * 8;
                    float sz, sr, sh;
                    dot3(hv4, w, bias[0], bias[1], bias[2], sz, sr, sh);
                    if (half == 0) {
                        float* dst = x2s[s & 7];
                        dst[col]       = sz;
                        dst[64 + col]  = sr;
                        dst[128 + col] = sh;
                    }
                }
            }
            asm volatile("cp.async.wait_group 2;" ::: "memory");
        } else {
            // ---------------- layer-2: steps 4k-8 .. 4k-5 ----------------
#pragma unroll
            for (int sub = 0; sub < 4; sub++) {
                const int s = 4 * k - 8 + sub;
                if (s >= 0 && s < T_LEN) {
                    const float4* hv4 = (const float4*)(h2s[(s - 1) & 7]) + half * 8;
                    const float xz = x2s[s & 7][col];
                    const float xr = x2s[s & 7][64 + col];
                    const float xh = x2s[s & 7][128 + col];
                    float az, ar, ah;
                    dot3(hv4, w, bias[0], bias[1], bias[2], az, ar, ah);
                    const float z  = sigf(xz + az);
                    const float r  = sigf(xr + ar);
                    const float hh = tanha(fmaf(r, ah, xh));
                    const float hold = h2s[(s - 1) & 7][col];
                    if (half == 0)
                        h2s[s & 7][col] = fmaf(z, hold - hh, hh);
                }
                if (sub < 3)
                    asm volatile("bar.sync 2, 128;" ::: "memory");
            }
        }
        __syncthreads();
    }

    // ---------------- Epilogue: sigmoid(h2[T-1] @ Wout + bout) ----------------
    if (tid < UDIM) red[tid] = h2s[(T_LEN - 1) & 7][tid] * Wout[tid];
    __syncthreads();
    if (tid == 0) {
        float s = bout[0];
#pragma unroll
        for (int k = 0; k < UDIM; k++) s += red[k];
        out[b] = 1.0f / (1.0f + __expf(-s));
    }
}

// ---------------------------------------------------------------------------
extern "C" void kernel_launch(void* const* d_in, const int* in_sizes, int n_in,
                              void* d_out, int out_size) {
    const int*   tokens = (const int*)  d_in[0];
    const float* emb    = (const float*)d_in[1];
    const float* W1     = (const float*)d_in[2];
    const float* U1     = (const float*)d_in[3];
    const float* b1     = (const float*)d_in[4];
    const float* W2     = (const float*)d_in[5];
    const float* U2     = (const float*)d_in[6];
    const float* b2     = (const float*)d_in[7];
    const float* Wout   = (const float*)d_in[8];
    const float* bout   = (const float*)d_in[9];

    build_tab<<<VOCAB, G3>>>(emb, W1, b1);
    gru_fused<<<BATCH, NTHR>>>(tokens, U1, b1, W2, U2, b2, Wout, bout,
                               (float*)d_out);
}